// round 16
// baseline (speedup 1.0000x reference)
#include <cuda_runtime.h>
#include <stdint.h>

// ---------------- problem constants ----------------------------------------
constexpr int cN = 268, cS = 32, cE = 1024, cB = 4;
constexpr float cScale = 0.03125f;           // 1/sqrt(1024)
constexpr size_t MM  = 1024ull * 1024ull;
constexpr int   TNK  = cS * cN;              // 8576
constexpr size_t NE  = (size_t)cN * cE;      // 274432
constexpr size_t SNE = (size_t)TNK * cE;     // 8781824

// ---------------- scratch (device globals) ----------------------------------
// g_W layout: [0..3] wq_b, [4] wq, [5..8] wk_b, [9] wk, [10..13] wv_b, [14] wv
__device__ __align__(1024) float g_W  [15 * MM];   // rounded weights
__device__ __align__(1024) float g_F2 [NE];        // rounded features
__device__ __align__(1024) float g_Q  [5 * NE];    // q = F@wq (rounded)
__device__ __align__(1024) float g_S  [4 * SNE];   // rounded snapshots [b][tm][e]
__device__ __align__(1024) float g_qh [5 * NE];    // q~ per branch + stage2
__device__ __align__(1024) float g_P  [(size_t)cB * cN * TNK];  // probs
__device__ __align__(1024) float g_UP [32 * NE];   // partials scratch (reused)
__device__ __align__(1024) float g_U  [4 * NE];    // U reduced+rounded
__device__ __align__(1024) float g_ms [4 * NE];    // branch outputs (rounded)
__device__ __align__(1024) float g_P2 [(size_t)cN * 4 * cN];    // stage2 probs
__device__ __align__(1024) float g_U2 [NE];        // stage2 U (rounded)

// ---------------- PTX helpers -----------------------------------------------
__device__ __forceinline__ uint32_t smem_u32(const void* p) {
    uint32_t a;
    asm("{ .reg .u64 t; cvta.to.shared.u64 t, %1; cvt.u32.u64 %0, t; }" : "=r"(a) : "l"(p));
    return a;
}
__device__ __forceinline__ void cp16(uint32_t dst, const void* src, int nbytes) {
    asm volatile("cp.async.cg.shared.global [%0], [%1], 16, %2;"
                 :: "r"(dst), "l"(src), "r"(nbytes));
}
__device__ __forceinline__ float roundtf(float f) {
    uint32_t r;
    asm("cvt.rna.tf32.f32 %0, %1;" : "=r"(r) : "f"(f));
    return __uint_as_float(r);
}
__device__ __forceinline__ void mma_tf32(float* c, const uint32_t* a, const uint32_t* b) {
    asm volatile(
        "mma.sync.aligned.m16n8k8.row.col.f32.tf32.tf32.f32 "
        "{%0,%1,%2,%3}, {%4,%5,%6,%7}, {%8,%9}, {%0,%1,%2,%3};"
        : "+f"(c[0]), "+f"(c[1]), "+f"(c[2]), "+f"(c[3])
        : "r"(a[0]), "r"(a[1]), "r"(a[2]), "r"(a[3]), "r"(b[0]), "r"(b[1]));
}

// ---------------- tf32 mma.sync GEMM (4-stage cp.async, 1 barrier/chunk) -----
// NT (bTrans=0): C = alpha * A[M,K] * B[Nv,K]^T  (B rows = Nv)
// NN (bTrans=1): C = alpha * A[M,K] * B[K,Nv]    (B rows = K)
// All operands pre-rounded to tf32. All base ptrs / K-splits 16B-aligned.
// k-permutation (pair form): HW (slice 2p, col t) <- logical k 16p+4t,
// (2p,t+4)<-+1, (2p+1,t)<-+2, (2p+1,t+4)<-+3; applied to A and B identically.
struct GArgs {
    const float* Aarr[32];
    const float* Barr[32];
    float* C;
    int M, Nv, K;
    int lda, ldb; long ldc; long cStride;
    int bTrans;
    float alpha;
};

constexpr int TM_ = 96, TN_ = 128, TK_ = 32;
constexpr int A_F        = TM_ * TK_;               // 3072 floats
constexpr int B_F        = TN_ * TK_;               // 4096 floats
constexpr int STAGE_F    = A_F + B_F;               // 7168 floats (28 KB)
constexpr int NSTAGE     = 4;
constexpr int SMEM_BYTES = NSTAGE * STAGE_F * 4;    // 114688

__device__ __forceinline__ int sw3f(int x) { return ((x & 1) << 2) | (x >> 1); }

__global__ void __launch_bounds__(256, 2) gemm_tc(GArgs g)
{
    extern __shared__ __align__(128) float smem[];
    const uint32_t sbase = smem_u32(smem);
    const int tid  = threadIdx.x;
    const int wid  = tid >> 5, lane = tid & 31;
    const int grp  = lane >> 2, tg = lane & 3;
    const int sw3g = sw3f(grp);

    const int z = blockIdx.z;
    const float* A = g.Aarr[z];
    const float* B = g.Barr[z];
    float* C = g.C + (long)z * g.cStride;

    const int m0 = blockIdx.y * TM_, n0 = blockIdx.x * TN_;
    const int M = g.M, Nv = g.Nv, K = g.K;
    const long lda = g.lda, ldb = g.ldb;
    const int nchunks = (K + TK_ - 1) / TK_;
    const int bT = g.bTrans;

    const int wrow0 = (wid & 1) * 48;
    const int wcol0 = (wid >> 1) * 32;

    float acc[3][4][4] = {};

    auto load_chunk = [&](int buf, int c) {
        const long k0 = (long)c * TK_;
        const uint32_t sA = sbase + buf * (STAGE_F * 4);
        const uint32_t sB = sA + A_F * 4;
#pragma unroll
        for (int i = 0; i < 3; ++i) {
            int l = tid + i * 256, r = l >> 3, seg = l & 7;
            long grow = m0 + r, gk = k0 + seg * 4;
            bool ok = (grow < M) && (gk < K);
            const float* src = ok ? (A + grow * lda + gk) : A;
            uint32_t off = (uint32_t)(r * 128 + (seg ^ sw3f(r & 7)) * 16);
            cp16(sA + off, src, ok ? 16 : 0);
        }
        if (!bT) {
#pragma unroll
            for (int i = 0; i < 4; ++i) {
                int l = tid + i * 256, r = l >> 3, seg = l & 7;
                long grow = n0 + r, gk = k0 + seg * 4;
                bool ok = (grow < Nv) && (gk < K);
                const float* src = ok ? (B + grow * ldb + gk) : B;
                uint32_t off = (uint32_t)(r * 128 + (seg ^ sw3f(r & 7)) * 16);
                cp16(sB + off, src, ok ? 16 : 0);
            }
        } else {
            // NN: B tile = 32 k-rows x 128 n-cols; [k][n] smem,
            // col s*4 XOR shift, shift = ((r>>2)&3)<<3
#pragma unroll
            for (int i = 0; i < 4; ++i) {
                int l = tid + i * 256, r = l >> 5, s = l & 31;
                long gk = k0 + r, gcol = n0 + s * 4;
                bool ok = (gk < K) && (gcol < Nv);
                const float* src = ok ? (B + gk * ldb + gcol) : B;
                uint32_t off = (uint32_t)(r * 512 + (((s * 4) ^ (((r >> 2) & 3) << 3)) << 2));
                cp16(sB + off, src, ok ? 16 : 0);
            }
        }
        asm volatile("cp.async.commit_group;");
    };

    load_chunk(0, 0);
    if (nchunks > 1) load_chunk(1, 1);

    int buf = 0;
    for (int c = 0; c < nchunks; ++c) {
        if (c + 2 < nchunks) {
            int nb = buf + 2; if (nb >= NSTAGE) nb -= NSTAGE;
            load_chunk(nb, c + 2);
            asm volatile("cp.async.wait_group 2;");
        } else if (c + 1 < nchunks) {
            asm volatile("cp.async.wait_group 1;");
        } else {
            asm volatile("cp.async.wait_group 0;");
        }
        // Single barrier per chunk: with NSTAGE=4 and write distance 2, the
        // buffer loaded at iteration c ((c+2)%4) was last read at c-2, and all
        // warps passed sync_{c-1} (thus finished compute c-2) before any warp
        // issues this load. Concurrent computes touch buffers c-1/c only.
        __syncthreads();

        const float* As = smem + buf * STAGE_F;
        const float* Bs = As + A_F;

#pragma unroll
        for (int p = 0; p < 2; ++p) {
            const int cs = ((4 * p + tg) ^ sw3g) << 2;   // float offset of 16B seg
            uint4 a0[3], a8[3];
#pragma unroll
            for (int mt = 0; mt < 3; ++mt) {
                int r0 = wrow0 + mt * 16 + grp;
                a0[mt] = *(const uint4*)&As[r0 * 32 + cs];
                a8[mt] = *(const uint4*)&As[(r0 + 8) * 32 + cs];
            }
            uint32_t bfr[4][4];
            if (!bT) {
#pragma unroll
                for (int nt = 0; nt < 4; ++nt) {
                    int rn = wcol0 + nt * 8 + grp;
                    uint4 w = *(const uint4*)&Bs[rn * 32 + cs];
                    bfr[nt][0] = w.x; bfr[nt][1] = w.y; bfr[nt][2] = w.z; bfr[nt][3] = w.w;
                }
            } else {
                const int rbase = 16 * p + 4 * tg;
#pragma unroll
                for (int nt = 0; nt < 4; ++nt) {
                    int nsw = (wcol0 + nt * 8 + grp) ^ (8 * tg);
                    bfr[nt][0] = *(const uint32_t*)&Bs[(rbase + 0) * TN_ + nsw];
                    bfr[nt][1] = *(const uint32_t*)&Bs[(rbase + 1) * TN_ + nsw];
                    bfr[nt][2] = *(const uint32_t*)&Bs[(rbase + 2) * TN_ + nsw];
                    bfr[nt][3] = *(const uint32_t*)&Bs[(rbase + 3) * TN_ + nsw];
                }
            }
#pragma unroll
            for (int mt = 0; mt < 3; ++mt) {
                uint32_t af[4] = { a0[mt].x, a8[mt].x, a0[mt].y, a8[mt].y };
#pragma unroll
                for (int nt = 0; nt < 4; ++nt) {
                    uint32_t bb[2] = { bfr[nt][0], bfr[nt][1] };
                    mma_tf32(acc[mt][nt], af, bb);
                }
            }
#pragma unroll
            for (int mt = 0; mt < 3; ++mt) {
                uint32_t af[4] = { a0[mt].z, a8[mt].z, a0[mt].w, a8[mt].w };
#pragma unroll
                for (int nt = 0; nt < 4; ++nt) {
                    uint32_t bb[2] = { bfr[nt][2], bfr[nt][3] };
                    mma_tf32(acc[mt][nt], af, bb);
                }
            }
        }
        if (++buf == NSTAGE) buf = 0;
    }

    const float alpha = g.alpha;
#pragma unroll
    for (int mt = 0; mt < 3; ++mt) {
#pragma unroll
        for (int nt = 0; nt < 4; ++nt) {
            long r0 = m0 + wrow0 + mt * 16 + grp;
            long cc = n0 + wcol0 + nt * 8 + tg * 2;
            if (cc < Nv) {
#pragma unroll
                for (int h = 0; h < 2; ++h) {
                    long rr = r0 + 8 * h;
                    if (rr < M) {
                        C[rr * g.ldc + cc]     = alpha * acc[mt][nt][2 * h];
                        C[rr * g.ldc + cc + 1] = alpha * acc[mt][nt][2 * h + 1];
                    }
                }
            }
        }
    }
}

// ---------------- rounded copies ---------------------------------------------
__global__ void round_s(const float* __restrict__ s1, const float* __restrict__ s2,
                        const float* __restrict__ s3, const float* __restrict__ s4)
{
    const int b = blockIdx.z;
    const float* sp = (b == 0) ? s1 : (b == 1) ? s2 : (b == 2) ? s3 : s4;
    const float4* src = (const float4*)sp;
    float4* dst = (float4*)(g_S + (size_t)b * SNE);
    const long n4 = (long)SNE / 4;
    for (long i = blockIdx.x * (long)blockDim.x + threadIdx.x; i < n4;
         i += (long)gridDim.x * blockDim.x) {
        float4 v = src[i];
        v.x = roundtf(v.x); v.y = roundtf(v.y);
        v.z = roundtf(v.z); v.w = roundtf(v.w);
        dst[i] = v;
    }
}

__global__ void round_w(const float* __restrict__ wq_b, const float* __restrict__ wk_b,
                        const float* __restrict__ wv_b, const float* __restrict__ wq,
                        const float* __restrict__ wk,   const float* __restrict__ wv,
                        const float* __restrict__ feat)
{
    const int z = blockIdx.z;
    const float* src; float* dst; long n4;
    if (z < 4)        { src = wq_b + (size_t)z * MM;        dst = g_W + (size_t)z * MM;  n4 = (long)MM / 4; }
    else if (z == 4)  { src = wq;                           dst = g_W + 4 * MM;          n4 = (long)MM / 4; }
    else if (z < 9)   { src = wk_b + (size_t)(z - 5) * MM;  dst = g_W + (size_t)z * MM;  n4 = (long)MM / 4; }
    else if (z == 9)  { src = wk;                           dst = g_W + 9 * MM;          n4 = (long)MM / 4; }
    else if (z < 14)  { src = wv_b + (size_t)(z - 10) * MM; dst = g_W + (size_t)z * MM;  n4 = (long)MM / 4; }
    else if (z == 14) { src = wv;                           dst = g_W + 14 * MM;         n4 = (long)MM / 4; }
    else              { src = feat;                         dst = g_F2;                  n4 = (long)NE / 4; }
    const float4* s4 = (const float4*)src;
    float4* d4 = (float4*)dst;
    for (long i = blockIdx.x * (long)blockDim.x + threadIdx.x; i < n4;
         i += (long)gridDim.x * blockDim.x) {
        float4 v = s4[i];
        v.x = roundtf(v.x); v.y = roundtf(v.y);
        v.z = roundtf(v.z); v.w = roundtf(v.w);
        d4[i] = v;
    }
}

// ---------------- generic batched split-K reduce -----------------------------
__global__ void reduce_n(const float4* __restrict__ src, float4* __restrict__ dst,
                         long part4, long n4, int nparts, int doRound,
                         long srcZ4, long dstZ4)
{
    long i = blockIdx.x * (long)blockDim.x + threadIdx.x;
    if (i >= n4) return;
    const float4* s = src + (long)blockIdx.z * srcZ4 + i;
    float4 r = s[0];
    for (int p = 1; p < nparts; ++p) {
        float4 v = s[(long)p * part4];
        r.x += v.x; r.y += v.y; r.z += v.z; r.w += v.w;
    }
    if (doRound) { r.x = roundtf(r.x); r.y = roundtf(r.y); r.z = roundtf(r.z); r.w = roundtf(r.w); }
    dst[(long)blockIdx.z * dstZ4 + i] = r;
}

// ---------------- softmax (warp per row of 268; rounds output) ---------------
__global__ __launch_bounds__(256) void softmax_kernel(float* __restrict__ base, int rows)
{
    int w = (blockIdx.x * blockDim.x + threadIdx.x) >> 5;
    int lane = threadIdx.x & 31;
    if (w >= rows) return;
    float* row = base + (size_t)w * cN;

    float v[9];
    float m = -1e30f;
#pragma unroll
    for (int j = 0; j < 9; ++j) {
        int c = lane + 32 * j;
        v[j] = (c < cN) ? row[c] : -1e30f;
        m = fmaxf(m, v[j]);
    }
#pragma unroll
    for (int o = 16; o; o >>= 1) m = fmaxf(m, __shfl_xor_sync(0xffffffffu, m, o));
    float s = 0.f;
#pragma unroll
    for (int j = 0; j < 9; ++j) { v[j] = expf(v[j] - m); s += v[j]; }
#pragma unroll
    for (int o = 16; o; o >>= 1) s += __shfl_xor_sync(0xffffffffu, s, o);
    float inv = 1.f / s;
#pragma unroll
    for (int j = 0; j < 9; ++j) {
        int c = lane + 32 * j;
        if (c < cN) row[c] = roundtf(v[j] * inv);
    }
}

// softmax over summed partials
__global__ __launch_bounds__(256) void softmax_sum(const float* __restrict__ src,
                                                   float* __restrict__ dst,
                                                   int rows, int nparts, long partStride)
{
    int w = (blockIdx.x * blockDim.x + threadIdx.x) >> 5;
    int lane = threadIdx.x & 31;
    if (w >= rows) return;
    const float* rowp = src + (size_t)w * cN;
    float* rowd = dst + (size_t)w * cN;

    float v[9];
    float m = -1e30f;
#pragma unroll
    for (int j = 0; j < 9; ++j) {
        int c = lane + 32 * j;
        float acc = 0.f;
        if (c < cN)
            for (int p = 0; p < nparts; ++p) acc += rowp[(long)p * partStride + c];
        v[j] = (c < cN) ? acc : -1e30f;
        m = fmaxf(m, v[j]);
    }
#pragma unroll
    for (int o = 16; o; o >>= 1) m = fmaxf(m, __shfl_xor_sync(0xffffffffu, m, o));
    float s = 0.f;
#pragma unroll
    for (int j = 0; j < 9; ++j) { v[j] = expf(v[j] - m); s += v[j]; }
#pragma unroll
    for (int o = 16; o; o >>= 1) s += __shfl_xor_sync(0xffffffffu, s, o);
    float inv = 1.f / s;
#pragma unroll
    for (int j = 0; j < 9; ++j) {
        int c = lane + 32 * j;
        if (c < cN) rowd[c] = roundtf(v[j] * inv);
    }
}

// ---------------- launch -----------------------------------------------------
static inline void launch_gemm(const GArgs& a, int batch)
{
    dim3 grid((a.Nv + TN_ - 1) / TN_, (a.M + TM_ - 1) / TM_, batch);
    gemm_tc<<<grid, 256, SMEM_BYTES>>>(a);
}

extern "C" void kernel_launch(void* const* d_in, const int* in_sizes, int n_in,
                              void* d_out, int out_size)
{
    const float* features = (const float*)d_in[0];
    const float* s1 = (const float*)d_in[1];
    const float* s2 = (const float*)d_in[2];
    const float* s3 = (const float*)d_in[3];
    const float* s4 = (const float*)d_in[4];
    const float* wq_b = (const float*)d_in[5];
    const float* wk_b = (const float*)d_in[6];
    const float* wv_b = (const float*)d_in[7];
    const float* wq   = (const float*)d_in[8];
    const float* wk   = (const float*)d_in[9];
    const float* wv   = (const float*)d_in[10];
    float* out = (float*)d_out;

    cudaFuncSetAttribute(gemm_tc, cudaFuncAttributeMaxDynamicSharedMemorySize, SMEM_BYTES);

    float *W, *F2, *Q, *S, *QH, *P, *UP, *U, *MSp, *P2, *U2;
    cudaGetSymbolAddress((void**)&W,   g_W);
    cudaGetSymbolAddress((void**)&F2,  g_F2);
    cudaGetSymbolAddress((void**)&Q,   g_Q);
    cudaGetSymbolAddress((void**)&S,   g_S);
    cudaGetSymbolAddress((void**)&QH,  g_qh);
    cudaGetSymbolAddress((void**)&P,   g_P);
    cudaGetSymbolAddress((void**)&UP,  g_UP);
    cudaGetSymbolAddress((void**)&U,   g_U);
    cudaGetSymbolAddress((void**)&MSp, g_ms);
    cudaGetSymbolAddress((void**)&P2,  g_P2);
    cudaGetSymbolAddress((void**)&U2,  g_U2);

    const long NE4 = (long)NE / 4;

    // 0) pre-round snapshots, weights, features
    round_s<<<dim3(512, 1, 4), 256>>>(s1, s2, s3, s4);
    round_w<<<dim3(256, 1, 16), 256>>>(wq_b, wk_b, wv_b, wq, wk, wv, features);

    // 1) q[z] = F2 @ wq_z  (NN), split-K x2 -> g_Q
    {
        GArgs a{};
        for (int z = 0; z < 10; ++z) {
            int w = z >> 1, ks = z & 1;
            a.Aarr[z] = F2 + ks * 512;
            a.Barr[z] = W + (size_t)w * MM + (size_t)ks * 512 * 1024;
        }
        a.C = UP; a.M = cN; a.Nv = 1024; a.K = 512;
        a.lda = 1024; a.ldb = 1024; a.ldc = 1024; a.cStride = (long)NE;
        a.bTrans = 1; a.alpha = 1.f;
        launch_gemm(a, 10);
        reduce_n<<<dim3((int)((NE4 + 255) / 256), 1, 5), 256>>>(
            (const float4*)UP, (float4*)Q, NE4, NE4, 2, 1, 2 * NE4, NE4);
    }

    // 2) q~[z] = q_z @ wk_z^T  (NT), split-K x2 -> g_qh
    {
        GArgs a{};
        for (int z = 0; z < 10; ++z) {
            int w = z >> 1, ks = z & 1;
            a.Aarr[z] = Q + (size_t)w * NE + ks * 512;
            a.Barr[z] = W + (size_t)(5 + w) * MM + ks * 512;
        }
        a.C = UP; a.M = cN; a.Nv = 1024; a.K = 512;
        a.lda = 1024; a.ldb = 1024; a.ldc = 1024; a.cStride = (long)NE;
        a.bTrans = 0; a.alpha = 1.f;
        launch_gemm(a, 10);
        reduce_n<<<dim3((int)((NE4 + 255) / 256), 1, 5), 256>>>(
            (const float4*)UP, (float4*)QH, NE4, NE4, 2, 1, 2 * NE4, NE4);
    }

    // 3) stage-1 scores: P[b] = scale * q~_b @ S_b^T  (NT)
    {
        GArgs a{};
        for (int b = 0; b < 4; ++b) { a.Aarr[b] = QH + (size_t)b * NE; a.Barr[b] = S + (size_t)b * SNE; }
        a.C = P; a.M = cN; a.Nv = TNK; a.K = 1024;
        a.lda = 1024; a.ldb = cE; a.ldc = (long)TNK; a.cStride = (long)cN * TNK;
        a.bTrans = 0; a.alpha = cScale;
        launch_gemm(a, 4);
    }

    // 4) softmax over 34304 segments of 268
    {
        int rows = cB * cN * cS;
        softmax_kernel<<<(rows + 7) / 8, 256>>>(P, rows);
    }

    // 5) U: NN over pre-rounded S, split-K x8 (K=1072 each), z = b*8+ks
    {
        GArgs a{};
        for (int z = 0; z < 32; ++z) {
            int b = z >> 3, ks = z & 7;
            a.Aarr[z] = P + (size_t)b * cN * TNK + (size_t)ks * 1072;
            a.Barr[z] = S + (size_t)b * SNE + (size_t)ks * 1072 * cE;
        }
        a.C = UP; a.M = cN; a.Nv = 1024; a.K = 1072;
        a.lda = TNK; a.ldb = cE; a.ldc = 1024; a.cStride = (long)NE;
        a.bTrans = 1; a.alpha = 1.f;
        launch_gemm(a, 32);
        reduce_n<<<dim3((int)((NE4 + 255) / 256), 1, 4), 256>>>(
            (const float4*)UP, (float4*)U, NE4, NE4, 8, 1, 8 * NE4, NE4);
    }

    // 6) ms_b = U_b @ wv_b  (NN, rounded wv), split-K x8 (K=128), z=b*8+ks
    {
        GArgs a{};
        for (int z = 0; z < 32; ++z) {
            int b = z >> 3, ks = z & 7;
            a.Aarr[z] = U + (size_t)b * NE + ks * 128;
            a.Barr[z] = W + (size_t)(10 + b) * MM + (size_t)ks * 128 * 1024;
        }
        a.C = UP; a.M = cN; a.Nv = 1024; a.K = 128;
        a.lda = 1024; a.ldb = 1024; a.ldc = 1024; a.cStride = (long)NE;
        a.bTrans = 1; a.alpha = 1.f;
        launch_gemm(a, 32);
        reduce_n<<<dim3((int)((NE4 + 255) / 256), 1, 4), 256>>>(
            (const float4*)UP, (float4*)MSp, NE4, NE4, 8, 1, 8 * NE4, NE4);
    }

    // 7) stage-2 scores: split-K x8 (K=128), partial-sum fused into softmax
    {
        GArgs a{};
        for (int z = 0; z < 8; ++z) { a.Aarr[z] = QH + 4 * NE + z * 128; a.Barr[z] = MSp + z * 128; }
        a.C = UP; a.M = cN; a.Nv = 4 * cN; a.K = 128;
        a.lda = 1024; a.ldb = 1024; a.ldc = (long)(4 * cN); a.cStride = (long)(cN * 4 * cN);
        a.bTrans = 0; a.alpha = cScale;
        launch_gemm(a, 8);
        softmax_sum<<<(4 * cN + 7) / 8, 256>>>(UP, P2, 4 * cN, 8, (long)(cN * 4 * cN));
    }

    // 8) U2 = P2 @ ms  (NN, split-K x4 of K=1072: 268 each, 16B-aligned)
    {
        GArgs a{};
        for (int z = 0; z < 4; ++z) { a.Aarr[z] = P2 + z * 268; a.Barr[z] = MSp + (size_t)z * 268 * 1024; }
        a.C = UP; a.M = cN; a.Nv = 1024; a.K = 268;
        a.lda = 4 * cN; a.ldb = 1024; a.ldc = 1024; a.cStride = (long)NE;
        a.bTrans = 1; a.alpha = 1.f;
        launch_gemm(a, 4);
        reduce_n<<<(int)((NE4 + 255) / 256), 256>>>(
            (const float4*)UP, (float4*)U2, NE4, NE4, 4, 1, 0, 0);
    }

    // 9) out = U2 @ wv  (NN, rounded wv, split-K x8, K=128)
    {
        GArgs a{};
        for (int z = 0; z < 8; ++z) { a.Aarr[z] = U2 + z * 128; a.Barr[z] = W + 14 * MM + (size_t)z * 128 * 1024; }
        a.C = UP; a.M = cN; a.Nv = 1024; a.K = 128;
        a.lda = 1024; a.ldb = 1024; a.ldc = 1024; a.cStride = (long)NE;
        a.bTrans = 1; a.alpha = 1.f;
        launch_gemm(a, 8);
        reduce_n<<<(int)((NE4 + 255) / 256), 256>>>(
            (const float4*)UP, (float4*)out, NE4, NE4, 8, 0, 0, 0);
    }
}

// round 17
// speedup vs baseline: 1.0004x; 1.0004x over previous
#include <cuda_runtime.h>
#include <stdint.h>

// ---------------- problem constants ----------------------------------------
constexpr int cN = 268, cS = 32, cE = 1024, cB = 4;
constexpr float cScale = 0.03125f;           // 1/sqrt(1024)
constexpr size_t MM  = 1024ull * 1024ull;
constexpr int   TNK  = cS * cN;              // 8576
constexpr size_t NE  = (size_t)cN * cE;      // 274432
constexpr size_t SNE = (size_t)TNK * cE;     // 8781824

// ---------------- scratch (device globals) ----------------------------------
__device__ __align__(1024) float g_Q  [5 * NE];    // q = F@wq (rounded)
__device__ __align__(1024) float g_S  [4 * SNE];   // rounded snapshots [b][tm][e]
__device__ __align__(1024) float g_qh [5 * NE];    // q~ per branch + stage2
__device__ __align__(1024) float g_P  [(size_t)cB * cN * TNK];  // probs
__device__ __align__(1024) float g_UP [32 * NE];   // partials scratch (reused)
__device__ __align__(1024) float g_U  [4 * NE];    // U reduced+rounded
__device__ __align__(1024) float g_ms [4 * NE];    // branch outputs (rounded)
__device__ __align__(1024) float g_P2 [(size_t)cN * 4 * cN];    // stage2 probs
__device__ __align__(1024) float g_U2 [NE];        // stage2 U (rounded)

// ---------------- PTX helpers -----------------------------------------------
__device__ __forceinline__ uint32_t smem_u32(const void* p) {
    uint32_t a;
    asm("{ .reg .u64 t; cvta.to.shared.u64 t, %1; cvt.u32.u64 %0, t; }" : "=r"(a) : "l"(p));
    return a;
}
__device__ __forceinline__ void cp16(uint32_t dst, const void* src, int nbytes) {
    asm volatile("cp.async.cg.shared.global [%0], [%1], 16, %2;"
                 :: "r"(dst), "l"(src), "r"(nbytes));
}
__device__ __forceinline__ float roundtf(float f) {
    uint32_t r;
    asm("cvt.rna.tf32.f32 %0, %1;" : "=r"(r) : "f"(f));
    return __uint_as_float(r);
}
__device__ __forceinline__ void mma_tf32(float* c, const uint32_t* a, const uint32_t* b) {
    asm volatile(
        "mma.sync.aligned.m16n8k8.row.col.f32.tf32.tf32.f32 "
        "{%0,%1,%2,%3}, {%4,%5,%6,%7}, {%8,%9}, {%0,%1,%2,%3};"
        : "+f"(c[0]), "+f"(c[1]), "+f"(c[2]), "+f"(c[3])
        : "r"(a[0]), "r"(a[1]), "r"(a[2]), "r"(a[3]), "r"(b[0]), "r"(b[1]));
}

// ---------------- tf32 mma.sync GEMM (4-stage cp.async, 1 barrier/chunk) -----
// NT (bTrans=0): C = alpha * A[M,K] * B[Nv,K]^T  (B rows = Nv)
// NN (bTrans=1): C = alpha * A[M,K] * B[K,Nv]    (B rows = K)
// roundA/roundB: RNA-round the A/B tile in smem (for raw fp32 operands).
// All base ptrs / K-split offsets must be 16-byte aligned.
// k-permutation (pair form): HW (slice 2p, col t) <- logical k 16p+4t,
// (2p,t+4)<-+1, (2p+1,t)<-+2, (2p+1,t+4)<-+3; applied to A and B identically.
struct GArgs {
    const float* Aarr[32];
    const float* Barr[32];
    float* C;
    int M, Nv, K;
    int lda, ldb; long ldc; long cStride;
    int roundA, roundB, bTrans;
    float alpha;
};

constexpr int TM_ = 96, TN_ = 128, TK_ = 32;
constexpr int A_F        = TM_ * TK_;               // 3072 floats
constexpr int B_F        = TN_ * TK_;               // 4096 floats
constexpr int STAGE_F    = A_F + B_F;               // 7168 floats (28 KB)
constexpr int NSTAGE     = 4;
constexpr int SMEM_BYTES = NSTAGE * STAGE_F * 4;    // 114688

__device__ __forceinline__ int sw3f(int x) { return ((x & 1) << 2) | (x >> 1); }

__global__ void __launch_bounds__(256, 2) gemm_tc(GArgs g)
{
    extern __shared__ __align__(128) float smem[];
    const uint32_t sbase = smem_u32(smem);
    const int tid  = threadIdx.x;
    const int wid  = tid >> 5, lane = tid & 31;
    const int grp  = lane >> 2, tg = lane & 3;
    const int sw3g = sw3f(grp);

    const int z = blockIdx.z;
    const float* A = g.Aarr[z];
    const float* B = g.Barr[z];
    float* C = g.C + (long)z * g.cStride;

    const int m0 = blockIdx.y * TM_, n0 = blockIdx.x * TN_;
    const int M = g.M, Nv = g.Nv, K = g.K;
    const long lda = g.lda, ldb = g.ldb;
    const int nchunks = (K + TK_ - 1) / TK_;
    const int bT = g.bTrans;

    const int wrow0 = (wid & 1) * 48;
    const int wcol0 = (wid >> 1) * 32;

    float acc[3][4][4] = {};

    auto load_chunk = [&](int buf, int c) {
        const long k0 = (long)c * TK_;
        const uint32_t sA = sbase + buf * (STAGE_F * 4);
        const uint32_t sB = sA + A_F * 4;
#pragma unroll
        for (int i = 0; i < 3; ++i) {
            int l = tid + i * 256, r = l >> 3, seg = l & 7;
            long grow = m0 + r, gk = k0 + seg * 4;
            bool ok = (grow < M) && (gk < K);
            const float* src = ok ? (A + grow * lda + gk) : A;
            uint32_t off = (uint32_t)(r * 128 + (seg ^ sw3f(r & 7)) * 16);
            cp16(sA + off, src, ok ? 16 : 0);
        }
        if (!bT) {
#pragma unroll
            for (int i = 0; i < 4; ++i) {
                int l = tid + i * 256, r = l >> 3, seg = l & 7;
                long grow = n0 + r, gk = k0 + seg * 4;
                bool ok = (grow < Nv) && (gk < K);
                const float* src = ok ? (B + grow * ldb + gk) : B;
                uint32_t off = (uint32_t)(r * 128 + (seg ^ sw3f(r & 7)) * 16);
                cp16(sB + off, src, ok ? 16 : 0);
            }
        } else {
            // NN: B tile = 32 k-rows x 128 n-cols; [k][n] smem,
            // col s*4 XOR shift, shift = ((r>>2)&3)<<3
#pragma unroll
            for (int i = 0; i < 4; ++i) {
                int l = tid + i * 256, r = l >> 5, s = l & 31;
                long gk = k0 + r, gcol = n0 + s * 4;
                bool ok = (gk < K) && (gcol < Nv);
                const float* src = ok ? (B + gk * ldb + gcol) : B;
                uint32_t off = (uint32_t)(r * 512 + (((s * 4) ^ (((r >> 2) & 3) << 3)) << 2));
                cp16(sB + off, src, ok ? 16 : 0);
            }
        }
        asm volatile("cp.async.commit_group;");
    };

    load_chunk(0, 0);
    if (nchunks > 1) load_chunk(1, 1);

    int buf = 0;
    for (int c = 0; c < nchunks; ++c) {
        if (c + 2 < nchunks) {
            int nb = buf + 2; if (nb >= NSTAGE) nb -= NSTAGE;
            load_chunk(nb, c + 2);
            asm volatile("cp.async.wait_group 2;");
        } else if (c + 1 < nchunks) {
            asm volatile("cp.async.wait_group 1;");
        } else {
            asm volatile("cp.async.wait_group 0;");
        }
        // Single barrier per chunk: with NSTAGE=4 and write distance 2, the
        // buffer loaded at iteration c ((c+2)%4) was last read at c-2, and all
        // warps passed sync_{c-1} (thus finished compute c-2) before any warp
        // issues this load. Concurrent computes touch buffers c-1/c only.
        __syncthreads();

        if (g.roundA || g.roundB) {
            if (g.roundA) {
                float4* ap = (float4*)(smem + buf * STAGE_F);
#pragma unroll
                for (int q = 0; q < 3; ++q) {
                    float4 v = ap[tid + q * 256];
                    v.x = roundtf(v.x); v.y = roundtf(v.y);
                    v.z = roundtf(v.z); v.w = roundtf(v.w);
                    ap[tid + q * 256] = v;
                }
            }
            if (g.roundB) {
                float4* bp = (float4*)(smem + buf * STAGE_F + A_F);
#pragma unroll
                for (int q = 0; q < 4; ++q) {
                    float4 v = bp[tid + q * 256];
                    v.x = roundtf(v.x); v.y = roundtf(v.y);
                    v.z = roundtf(v.z); v.w = roundtf(v.w);
                    bp[tid + q * 256] = v;
                }
            }
            __syncthreads();
        }

        const float* As = smem + buf * STAGE_F;
        const float* Bs = As + A_F;

#pragma unroll
        for (int p = 0; p < 2; ++p) {
            const int cs = ((4 * p + tg) ^ sw3g) << 2;   // float offset of 16B seg
            uint4 a0[3], a8[3];
#pragma unroll
            for (int mt = 0; mt < 3; ++mt) {
                int r0 = wrow0 + mt * 16 + grp;
                a0[mt] = *(const uint4*)&As[r0 * 32 + cs];
                a8[mt] = *(const uint4*)&As[(r0 + 8) * 32 + cs];
            }
            uint32_t bfr[4][4];
            if (!bT) {
#pragma unroll
                for (int nt = 0; nt < 4; ++nt) {
                    int rn = wcol0 + nt * 8 + grp;
                    uint4 w = *(const uint4*)&Bs[rn * 32 + cs];
                    bfr[nt][0] = w.x; bfr[nt][1] = w.y; bfr[nt][2] = w.z; bfr[nt][3] = w.w;
                }
            } else {
                const int rbase = 16 * p + 4 * tg;
#pragma unroll
                for (int nt = 0; nt < 4; ++nt) {
                    int nsw = (wcol0 + nt * 8 + grp) ^ (8 * tg);
                    bfr[nt][0] = *(const uint32_t*)&Bs[(rbase + 0) * TN_ + nsw];
                    bfr[nt][1] = *(const uint32_t*)&Bs[(rbase + 1) * TN_ + nsw];
                    bfr[nt][2] = *(const uint32_t*)&Bs[(rbase + 2) * TN_ + nsw];
                    bfr[nt][3] = *(const uint32_t*)&Bs[(rbase + 3) * TN_ + nsw];
                }
            }
#pragma unroll
            for (int mt = 0; mt < 3; ++mt) {
                uint32_t af[4] = { a0[mt].x, a8[mt].x, a0[mt].y, a8[mt].y };
#pragma unroll
                for (int nt = 0; nt < 4; ++nt) {
                    uint32_t bb[2] = { bfr[nt][0], bfr[nt][1] };
                    mma_tf32(acc[mt][nt], af, bb);
                }
            }
#pragma unroll
            for (int mt = 0; mt < 3; ++mt) {
                uint32_t af[4] = { a0[mt].z, a8[mt].z, a0[mt].w, a8[mt].w };
#pragma unroll
                for (int nt = 0; nt < 4; ++nt) {
                    uint32_t bb[2] = { bfr[nt][2], bfr[nt][3] };
                    mma_tf32(acc[mt][nt], af, bb);
                }
            }
        }
        if (++buf == NSTAGE) buf = 0;
    }

    const float alpha = g.alpha;
#pragma unroll
    for (int mt = 0; mt < 3; ++mt) {
#pragma unroll
        for (int nt = 0; nt < 4; ++nt) {
            long r0 = m0 + wrow0 + mt * 16 + grp;
            long cc = n0 + wcol0 + nt * 8 + tg * 2;
            if (cc < Nv) {
#pragma unroll
                for (int h = 0; h < 2; ++h) {
                    long rr = r0 + 8 * h;
                    if (rr < M) {
                        C[rr * g.ldc + cc]     = alpha * acc[mt][nt][2 * h];
                        C[rr * g.ldc + cc + 1] = alpha * acc[mt][nt][2 * h + 1];
                    }
                }
            }
        }
    }
}

// ---------------- rounded copy of snapshots ---------------------------------
__global__ void round_s(const float* __restrict__ s1, const float* __restrict__ s2,
                        const float* __restrict__ s3, const float* __restrict__ s4)
{
    const int b = blockIdx.z;
    const float* sp = (b == 0) ? s1 : (b == 1) ? s2 : (b == 2) ? s3 : s4;
    const float4* src = (const float4*)sp;
    float4* dst = (float4*)(g_S + (size_t)b * SNE);
    const long n4 = (long)SNE / 4;
    for (long i = blockIdx.x * (long)blockDim.x + threadIdx.x; i < n4;
         i += (long)gridDim.x * blockDim.x) {
        float4 v = src[i];
        v.x = roundtf(v.x); v.y = roundtf(v.y);
        v.z = roundtf(v.z); v.w = roundtf(v.w);
        dst[i] = v;
    }
}

// ---------------- generic batched split-K reduce -----------------------------
__global__ void reduce_n(const float4* __restrict__ src, float4* __restrict__ dst,
                         long part4, long n4, int nparts, int doRound,
                         long srcZ4, long dstZ4)
{
    long i = blockIdx.x * (long)blockDim.x + threadIdx.x;
    if (i >= n4) return;
    const float4* s = src + (long)blockIdx.z * srcZ4 + i;
    float4 r = s[0];
    for (int p = 1; p < nparts; ++p) {
        float4 v = s[(long)p * part4];
        r.x += v.x; r.y += v.y; r.z += v.z; r.w += v.w;
    }
    if (doRound) { r.x = roundtf(r.x); r.y = roundtf(r.y); r.z = roundtf(r.z); r.w = roundtf(r.w); }
    dst[(long)blockIdx.z * dstZ4 + i] = r;
}

// ---------------- softmax (warp per row of 268; rounds output) ---------------
__global__ __launch_bounds__(256) void softmax_kernel(float* __restrict__ base, int rows)
{
    int w = (blockIdx.x * blockDim.x + threadIdx.x) >> 5;
    int lane = threadIdx.x & 31;
    if (w >= rows) return;
    float* row = base + (size_t)w * cN;

    float v[9];
    float m = -1e30f;
#pragma unroll
    for (int j = 0; j < 9; ++j) {
        int c = lane + 32 * j;
        v[j] = (c < cN) ? row[c] : -1e30f;
        m = fmaxf(m, v[j]);
    }
#pragma unroll
    for (int o = 16; o; o >>= 1) m = fmaxf(m, __shfl_xor_sync(0xffffffffu, m, o));
    float s = 0.f;
#pragma unroll
    for (int j = 0; j < 9; ++j) { v[j] = expf(v[j] - m); s += v[j]; }
#pragma unroll
    for (int o = 16; o; o >>= 1) s += __shfl_xor_sync(0xffffffffu, s, o);
    float inv = 1.f / s;
#pragma unroll
    for (int j = 0; j < 9; ++j) {
        int c = lane + 32 * j;
        if (c < cN) row[c] = roundtf(v[j] * inv);
    }
}

// softmax over summed partials
__global__ __launch_bounds__(256) void softmax_sum(const float* __restrict__ src,
                                                   float* __restrict__ dst,
                                                   int rows, int nparts, long partStride)
{
    int w = (blockIdx.x * blockDim.x + threadIdx.x) >> 5;
    int lane = threadIdx.x & 31;
    if (w >= rows) return;
    const float* rowp = src + (size_t)w * cN;
    float* rowd = dst + (size_t)w * cN;

    float v[9];
    float m = -1e30f;
#pragma unroll
    for (int j = 0; j < 9; ++j) {
        int c = lane + 32 * j;
        float acc = 0.f;
        if (c < cN)
            for (int p = 0; p < nparts; ++p) acc += rowp[(long)p * partStride + c];
        v[j] = (c < cN) ? acc : -1e30f;
        m = fmaxf(m, v[j]);
    }
#pragma unroll
    for (int o = 16; o; o >>= 1) m = fmaxf(m, __shfl_xor_sync(0xffffffffu, m, o));
    float s = 0.f;
#pragma unroll
    for (int j = 0; j < 9; ++j) { v[j] = expf(v[j] - m); s += v[j]; }
#pragma unroll
    for (int o = 16; o; o >>= 1) s += __shfl_xor_sync(0xffffffffu, s, o);
    float inv = 1.f / s;
#pragma unroll
    for (int j = 0; j < 9; ++j) {
        int c = lane + 32 * j;
        if (c < cN) rowd[c] = roundtf(v[j] * inv);
    }
}

// ---------------- launch -----------------------------------------------------
static inline void launch_gemm(const GArgs& a, int batch)
{
    dim3 grid((a.Nv + TN_ - 1) / TN_, (a.M + TM_ - 1) / TM_, batch);
    gemm_tc<<<grid, 256, SMEM_BYTES>>>(a);
}

extern "C" void kernel_launch(void* const* d_in, const int* in_sizes, int n_in,
                              void* d_out, int out_size)
{
    const float* features = (const float*)d_in[0];
    const float* s1 = (const float*)d_in[1];
    const float* s2 = (const float*)d_in[2];
    const float* s3 = (const float*)d_in[3];
    const float* s4 = (const float*)d_in[4];
    const float* wq_b = (const float*)d_in[5];
    const float* wk_b = (const float*)d_in[6];
    const float* wv_b = (const float*)d_in[7];
    const float* wq   = (const float*)d_in[8];
    const float* wk   = (const float*)d_in[9];
    const float* wv   = (const float*)d_in[10];
    float* out = (float*)d_out;

    cudaFuncSetAttribute(gemm_tc, cudaFuncAttributeMaxDynamicSharedMemorySize, SMEM_BYTES);

    float *Q, *S, *QH, *P, *UP, *U, *MSp, *P2, *U2;
    cudaGetSymbolAddress((void**)&Q,   g_Q);
    cudaGetSymbolAddress((void**)&S,   g_S);
    cudaGetSymbolAddress((void**)&QH,  g_qh);
    cudaGetSymbolAddress((void**)&P,   g_P);
    cudaGetSymbolAddress((void**)&UP,  g_UP);
    cudaGetSymbolAddress((void**)&U,   g_U);
    cudaGetSymbolAddress((void**)&MSp, g_ms);
    cudaGetSymbolAddress((void**)&P2,  g_P2);
    cudaGetSymbolAddress((void**)&U2,  g_U2);

    const long NE4 = (long)NE / 4;

    // 0) pre-round snapshots (serves scores NT and U NN)
    round_s<<<dim3(512, 1, 4), 256>>>(s1, s2, s3, s4);

    // 1) q[z] = F @ wq_z  (NN, raw, rounded in smem), split-K x2 -> g_Q
    {
        GArgs a{};
        for (int z = 0; z < 10; ++z) {
            int w = z >> 1, ks = z & 1;
            const float* wqp = (w < 4) ? wq_b + (size_t)w * MM : wq;
            a.Aarr[z] = features + ks * 512;
            a.Barr[z] = wqp + (size_t)ks * 512 * 1024;
        }
        a.C = UP; a.M = cN; a.Nv = 1024; a.K = 512;
        a.lda = 1024; a.ldb = 1024; a.ldc = 1024; a.cStride = (long)NE;
        a.roundA = 1; a.roundB = 1; a.bTrans = 1; a.alpha = 1.f;
        launch_gemm(a, 10);
        reduce_n<<<dim3((int)((NE4 + 255) / 256), 1, 5), 256>>>(
            (const float4*)UP, (float4*)Q, NE4, NE4, 2, 1, 2 * NE4, NE4);
    }

    // 2) q~[z] = q_z @ wk_z^T  (NT, raw wk rounded), split-K x2 -> g_qh
    {
        GArgs a{};
        for (int z = 0; z < 10; ++z) {
            int w = z >> 1, ks = z & 1;
            const float* wkp = (w < 4) ? wk_b + (size_t)w * MM : wk;
            a.Aarr[z] = Q + (size_t)w * NE + ks * 512;
            a.Barr[z] = wkp + ks * 512;
        }
        a.C = UP; a.M = cN; a.Nv = 1024; a.K = 512;
        a.lda = 1024; a.ldb = 1024; a.ldc = 1024; a.cStride = (long)NE;
        a.roundA = 0; a.roundB = 1; a.bTrans = 0; a.alpha = 1.f;
        launch_gemm(a, 10);
        reduce_n<<<dim3((int)((NE4 + 255) / 256), 1, 5), 256>>>(
            (const float4*)UP, (float4*)QH, NE4, NE4, 2, 1, 2 * NE4, NE4);
    }

    // 3) stage-1 scores: P[b] = scale * q~_b @ S_b^T  (NT, pre-rounded S)
    {
        GArgs a{};
        for (int b = 0; b < 4; ++b) { a.Aarr[b] = QH + (size_t)b * NE; a.Barr[b] = S + (size_t)b * SNE; }
        a.C = P; a.M = cN; a.Nv = TNK; a.K = 1024;
        a.lda = 1024; a.ldb = cE; a.ldc = (long)TNK; a.cStride = (long)cN * TNK;
        a.roundA = 0; a.roundB = 0; a.bTrans = 0; a.alpha = cScale;
        launch_gemm(a, 4);
    }

    // 4) softmax over 34304 segments of 268
    {
        int rows = cB * cN * cS;
        softmax_kernel<<<(rows + 7) / 8, 256>>>(P, rows);
    }

    // 5) U: NN over pre-rounded S, split-K x8 (K=1072 each), z = b*8+ks
    {
        GArgs a{};
        for (int z = 0; z < 32; ++z) {
            int b = z >> 3, ks = z & 7;
            a.Aarr[z] = P + (size_t)b * cN * TNK + (size_t)ks * 1072;
            a.Barr[z] = S + (size_t)b * SNE + (size_t)ks * 1072 * cE;
        }
        a.C = UP; a.M = cN; a.Nv = 1024; a.K = 1072;
        a.lda = TNK; a.ldb = cE; a.ldc = 1024; a.cStride = (long)NE;
        a.roundA = 0; a.roundB = 0; a.bTrans = 1; a.alpha = 1.f;
        launch_gemm(a, 32);
        reduce_n<<<dim3((int)((NE4 + 255) / 256), 1, 4), 256>>>(
            (const float4*)UP, (float4*)U, NE4, NE4, 8, 1, 8 * NE4, NE4);
    }

    // 6) ms_b = U_b @ wv_b  (NN, raw wv_b rounded), split-K x8 (K=128), z=b*8+ks
    {
        GArgs a{};
        for (int z = 0; z < 32; ++z) {
            int b = z >> 3, ks = z & 7;
            a.Aarr[z] = U + (size_t)b * NE + ks * 128;
            a.Barr[z] = wv_b + (size_t)b * MM + (size_t)ks * 128 * 1024;
        }
        a.C = UP; a.M = cN; a.Nv = 1024; a.K = 128;
        a.lda = 1024; a.ldb = 1024; a.ldc = 1024; a.cStride = (long)NE;
        a.roundA = 0; a.roundB = 1; a.bTrans = 1; a.alpha = 1.f;
        launch_gemm(a, 32);
        reduce_n<<<dim3((int)((NE4 + 255) / 256), 1, 4), 256>>>(
            (const float4*)UP, (float4*)MSp, NE4, NE4, 8, 1, 8 * NE4, NE4);
    }

    // 7) stage-2 scores: split-K x8 (K=128), partial-sum fused into softmax
    {
        GArgs a{};
        for (int z = 0; z < 8; ++z) { a.Aarr[z] = QH + 4 * NE + z * 128; a.Barr[z] = MSp + z * 128; }
        a.C = UP; a.M = cN; a.Nv = 4 * cN; a.K = 128;
        a.lda = 1024; a.ldb = 1024; a.ldc = (long)(4 * cN); a.cStride = (long)(cN * 4 * cN);
        a.roundA = 0; a.roundB = 0; a.bTrans = 0; a.alpha = cScale;
        launch_gemm(a, 8);
        softmax_sum<<<(4 * cN + 7) / 8, 256>>>(UP, P2, 4 * cN, 8, (long)(cN * 4 * cN));
    }

    // 8) U2 = P2 @ ms  (NN, split-K x4 of K=1072: 268 each, 16B-aligned)
    {
        GArgs a{};
        for (int z = 0; z < 4; ++z) { a.Aarr[z] = P2 + z * 268; a.Barr[z] = MSp + (size_t)z * 268 * 1024; }
        a.C = UP; a.M = cN; a.Nv = 1024; a.K = 268;
        a.lda = 4 * cN; a.ldb = 1024; a.ldc = 1024; a.cStride = (long)NE;
        a.roundA = 0; a.roundB = 0; a.bTrans = 1; a.alpha = 1.f;
        launch_gemm(a, 4);
        reduce_n<<<(int)((NE4 + 255) / 256), 256>>>(
            (const float4*)UP, (float4*)U2, NE4, NE4, 4, 1, 0, 0);
    }

    // 9) out = U2 @ wv  (NN, raw wv rounded, split-K x8, K=128)
    {
        GArgs a{};
        for (int z = 0; z < 8; ++z) { a.Aarr[z] = U2 + z * 128; a.Barr[z] = wv + (size_t)z * 128 * 1024; }
        a.C = UP; a.M = cN; a.Nv = 1024; a.K = 128;
        a.lda = 1024; a.ldb = 1024; a.ldc = 1024; a.cStride = (long)NE;
        a.roundA = 0; a.roundB = 1; a.bTrans = 1; a.alpha = 1.f;
        launch_gemm(a, 8);
        reduce_n<<<(int)((NE4 + 255) / 256), 256>>>(
            (const float4*)UP, (float4*)out, NE4, NE4, 8, 0, 0, 0);
    }
}